// round 1
// baseline (speedup 1.0000x reference)
#include <cuda_runtime.h>
#include <math.h>

#define CDIM 256
#define NDIM 4096
#define BDIM 8

// scratch (allocation-free rule: __device__ globals)
__device__ float g_q[BDIM * NDIM * CDIM];
__device__ float g_k[BDIM * NDIM * CDIM];
__device__ float g_v[BDIM * NDIM * CDIM];

// ---------------------------------------------------------------------------
// Projection kernel: y[o,n] = sum_c W[o,c] * x[b,c,n] + bias[o]
// grid: (n_tiles=32, o_tiles=2, b*4+p=32), 256 threads, 128x128 tile, 8x8 micro
// p=0..2 -> q/k/v in [b][n][c] layout; p=3 -> proj directly into out [b][c][n]
// ---------------------------------------------------------------------------
__global__ __launch_bounds__(256) void proj_kernel(
    const float* __restrict__ x,
    const float* __restrict__ Wq, const float* __restrict__ bq,
    const float* __restrict__ Wk, const float* __restrict__ bk,
    const float* __restrict__ Wv, const float* __restrict__ bv,
    const float* __restrict__ Wp, const float* __restrict__ bp,
    float* __restrict__ out)
{
    __shared__ float sX[16 * 128];   // [cc][n]
    __shared__ float sW[16 * 128];   // [cc][o] (transposed on load)

    const int p  = blockIdx.z & 3;
    const int b  = blockIdx.z >> 2;
    const int n0 = blockIdx.x * 128;
    const int o0 = blockIdx.y * 128;

    const float* W; const float* bias;
    if (p == 0)      { W = Wq; bias = bq; }
    else if (p == 1) { W = Wk; bias = bk; }
    else if (p == 2) { W = Wv; bias = bv; }
    else             { W = Wp; bias = bp; }

    const int tid = threadIdx.x;
    const int it = tid >> 4;    // n micro: rows n0 + 8*it .. +7
    const int jt = tid & 15;    // o micro: chunks jt and jt+16 (o = 4jt+w, 64+4jt+w)

    float acc[8][8];
    #pragma unroll
    for (int r = 0; r < 8; r++)
        #pragma unroll
        for (int w = 0; w < 8; w++) acc[r][w] = 0.f;

    const float* xb = x + (size_t)b * CDIM * NDIM;

    for (int c0 = 0; c0 < CDIM; c0 += 16) {
        __syncthreads();
        // load x tile [16c][128n], coalesced float4
        #pragma unroll
        for (int q = 0; q < 2; q++) {
            int idx4 = tid + 256 * q;
            int cc  = idx4 >> 5;
            int nn4 = idx4 & 31;
            ((float4*)sX)[cc * 32 + nn4] =
                *(const float4*)(xb + (size_t)(c0 + cc) * NDIM + n0 + nn4 * 4);
        }
        // load W tile [128o][16c] -> transposed sW[cc][o]
        #pragma unroll
        for (int q = 0; q < 2; q++) {
            int idx4 = tid + 256 * q;
            int oo  = idx4 >> 2;
            int cc4 = idx4 & 3;
            float4 wv = *(const float4*)(W + (size_t)(o0 + oo) * CDIM + c0 + cc4 * 4);
            sW[(cc4 * 4 + 0) * 128 + oo] = wv.x;
            sW[(cc4 * 4 + 1) * 128 + oo] = wv.y;
            sW[(cc4 * 4 + 2) * 128 + oo] = wv.z;
            sW[(cc4 * 4 + 3) * 128 + oo] = wv.w;
        }
        __syncthreads();
        #pragma unroll
        for (int cc = 0; cc < 16; cc++) {
            float4 xa  = ((const float4*)(sX + cc * 128))[it * 2];      // broadcast
            float4 xb4 = ((const float4*)(sX + cc * 128))[it * 2 + 1];
            float4 wa  = ((const float4*)(sW + cc * 128))[jt];          // conflict-free
            float4 wb  = ((const float4*)(sW + cc * 128))[jt + 16];
            float xs[8] = {xa.x, xa.y, xa.z, xa.w, xb4.x, xb4.y, xb4.z, xb4.w};
            float ws[8] = {wa.x, wa.y, wa.z, wa.w, wb.x,  wb.y,  wb.z,  wb.w};
            #pragma unroll
            for (int r = 0; r < 8; r++)
                #pragma unroll
                for (int w = 0; w < 8; w++)
                    acc[r][w] += xs[r] * ws[w];
        }
    }

    float bias_v[8];
    #pragma unroll
    for (int w = 0; w < 8; w++) {
        int o = o0 + ((w < 4) ? (4 * jt + w) : (64 + 4 * jt + (w - 4)));
        bias_v[w] = bias[o];
    }

    if (p < 3) {
        // q/k/v layout: [b][n][c]
        float* dst = (p == 0) ? g_q : (p == 1) ? g_k : g_v;
        dst += (size_t)b * NDIM * CDIM;
        #pragma unroll
        for (int r = 0; r < 8; r++) {
            int n = n0 + it * 8 + r;
            float4 v1 = make_float4(acc[r][0] + bias_v[0], acc[r][1] + bias_v[1],
                                    acc[r][2] + bias_v[2], acc[r][3] + bias_v[3]);
            float4 v2 = make_float4(acc[r][4] + bias_v[4], acc[r][5] + bias_v[5],
                                    acc[r][6] + bias_v[6], acc[r][7] + bias_v[7]);
            *(float4*)(dst + (size_t)n * CDIM + o0 + 4 * jt)      = v1;
            *(float4*)(dst + (size_t)n * CDIM + o0 + 64 + 4 * jt) = v2;
        }
    } else {
        // proj layout: out[b][o][n] (residual base; attention adds h later)
        #pragma unroll
        for (int w = 0; w < 8; w++) {
            int o = o0 + ((w < 4) ? (4 * jt + w) : (64 + 4 * jt + (w - 4)));
            float* dst = out + ((size_t)b * CDIM + o) * NDIM + n0 + it * 8;
            float4 v1 = make_float4(acc[0][w] + bias_v[w], acc[1][w] + bias_v[w],
                                    acc[2][w] + bias_v[w], acc[3][w] + bias_v[w]);
            float4 v2 = make_float4(acc[4][w] + bias_v[w], acc[5][w] + bias_v[w],
                                    acc[6][w] + bias_v[w], acc[7][w] + bias_v[w]);
            *(float4*)(dst)     = v1;
            *(float4*)(dst + 4) = v2;
        }
    }
}

// ---------------------------------------------------------------------------
// Flash attention kernel. grid: (N/64=64 q-tiles, B=8). 256 threads.
// Per CTA: 64-row Q tile resident in smem; stream 64-row K/V tiles with
// online softmax. O accumulators in registers (4 rows x 16 cols / thread).
// Adds h into out (which already holds proj). smem = 208KB -> 1 CTA/SM.
// ---------------------------------------------------------------------------
__global__ __launch_bounds__(256, 1) void attn_kernel(float* __restrict__ out)
{
    extern __shared__ float sm[];
    float* sQ = sm;                    // [64][256]
    float* sK = sm + 64 * CDIM;        // [64][256], 16B-chunk swizzled
    float* sV = sm + 2 * 64 * CDIM;    // [64][256]
    float* sP = sm + 3 * 64 * CDIM;    // [64][64]

    const int b  = blockIdx.y;
    const int n0 = blockIdx.x * 64;
    const int tid = threadIdx.x;
    const int ti = tid >> 4;           // 0..15 -> S/O rows i0 = 4*ti
    const int tj = tid & 15;           // 0..15 -> S cols j0 = 4*tj / O col chunks
    const int i0 = ti * 4;
    const int j0 = tj * 4;
    const int xorq = tj & 7;

    const float* qb = g_q + ((size_t)b * NDIM + n0) * CDIM;
    const float* kb = g_k + (size_t)b * NDIM * CDIM;
    const float* vb = g_v + (size_t)b * NDIM * CDIM;

    // load Q tile (contiguous 64KB)
    for (int idx = tid; idx < 64 * CDIM / 4; idx += 256)
        ((float4*)sQ)[idx] = ((const float4*)qb)[idx];

    float m_run[4], l_run[4], acc[4][16];
    #pragma unroll
    for (int r = 0; r < 4; r++) {
        m_run[r] = -INFINITY; l_run[r] = 0.f;
        #pragma unroll
        for (int c = 0; c < 16; c++) acc[r][c] = 0.f;
    }

    for (int m0 = 0; m0 < NDIM; m0 += 64) {
        __syncthreads();   // prev PV reads of sK/sV/sP done
        // load K (swizzled) + V tiles, coalesced 512B per warp-instr
        for (int idx = tid; idx < 64 * 64; idx += 256) {
            int row = idx >> 6, kc = idx & 63;
            float4 kv4 = *(const float4*)(kb + (size_t)(m0 + row) * CDIM + kc * 4);
            float4 vv4 = *(const float4*)(vb + (size_t)(m0 + row) * CDIM + kc * 4);
            ((float4*)(sK + row * CDIM))[kc ^ ((row >> 2) & 7)] = kv4;
            ((float4*)(sV + row * CDIM))[kc] = vv4;
        }
        __syncthreads();

        // S = Q K^T : 4x4 micro per thread
        float s[4][4];
        #pragma unroll
        for (int r = 0; r < 4; r++)
            #pragma unroll
            for (int jr = 0; jr < 4; jr++) s[r][jr] = 0.f;

        for (int c4 = 0; c4 < 64; c4++) {
            float4 kv[4];
            int pc = c4 ^ xorq;
            #pragma unroll
            for (int jr = 0; jr < 4; jr++)
                kv[jr] = ((const float4*)(sK + (j0 + jr) * CDIM))[pc];
            #pragma unroll
            for (int r = 0; r < 4; r++) {
                float4 qv = ((const float4*)(sQ + (i0 + r) * CDIM))[c4]; // broadcast
                #pragma unroll
                for (int jr = 0; jr < 4; jr++)
                    s[r][jr] += qv.x * kv[jr].x + qv.y * kv[jr].y
                              + qv.z * kv[jr].z + qv.w * kv[jr].w;
            }
        }

        // online softmax (row stats shared across the 16-lane half-warp)
        #pragma unroll
        for (int r = 0; r < 4; r++) {
            float sv[4];
            float mloc = -INFINITY;
            #pragma unroll
            for (int jr = 0; jr < 4; jr++) {
                sv[jr] = s[r][jr] * 0.0625f;       // scale = C^-0.5 = 1/16
                mloc = fmaxf(mloc, sv[jr]);
            }
            #pragma unroll
            for (int o = 8; o > 0; o >>= 1)
                mloc = fmaxf(mloc, __shfl_xor_sync(0xffffffffu, mloc, o));
            float mn = fmaxf(m_run[r], mloc);
            float alpha = __expf(m_run[r] - mn);   // 0 on first tile
            m_run[r] = mn;
            float pr[4], lloc = 0.f;
            #pragma unroll
            for (int jr = 0; jr < 4; jr++) { pr[jr] = __expf(sv[jr] - mn); lloc += pr[jr]; }
            #pragma unroll
            for (int o = 8; o > 0; o >>= 1)
                lloc += __shfl_xor_sync(0xffffffffu, lloc, o);
            l_run[r] = l_run[r] * alpha + lloc;
            #pragma unroll
            for (int c = 0; c < 16; c++) acc[r][c] *= alpha;
            *(float4*)(sP + (i0 + r) * 64 + j0) = make_float4(pr[0], pr[1], pr[2], pr[3]);
        }
        __syncthreads();

        // O += P V : rows i0..i0+3, col chunks tj + 16*kk (conflict-free)
        for (int j = 0; j < 64; j++) {
            float p0 = sP[(i0 + 0) * 64 + j];      // broadcast
            float p1 = sP[(i0 + 1) * 64 + j];
            float p2 = sP[(i0 + 2) * 64 + j];
            float p3 = sP[(i0 + 3) * 64 + j];
            #pragma unroll
            for (int kk = 0; kk < 4; kk++) {
                float4 vv = ((const float4*)(sV + j * CDIM))[tj + 16 * kk];
                acc[0][kk * 4 + 0] += p0 * vv.x; acc[0][kk * 4 + 1] += p0 * vv.y;
                acc[0][kk * 4 + 2] += p0 * vv.z; acc[0][kk * 4 + 3] += p0 * vv.w;
                acc[1][kk * 4 + 0] += p1 * vv.x; acc[1][kk * 4 + 1] += p1 * vv.y;
                acc[1][kk * 4 + 2] += p1 * vv.z; acc[1][kk * 4 + 3] += p1 * vv.w;
                acc[2][kk * 4 + 0] += p2 * vv.x; acc[2][kk * 4 + 1] += p2 * vv.y;
                acc[2][kk * 4 + 2] += p2 * vv.z; acc[2][kk * 4 + 3] += p2 * vv.w;
                acc[3][kk * 4 + 0] += p3 * vv.x; acc[3][kk * 4 + 1] += p3 * vv.y;
                acc[3][kk * 4 + 2] += p3 * vv.z; acc[3][kk * 4 + 3] += p3 * vv.w;
            }
        }
    }

    // epilogue: h = O / l, out[b][c][n0+i] += h (4 consecutive n per float4)
    float inv[4];
    #pragma unroll
    for (int r = 0; r < 4; r++) inv[r] = 1.0f / l_run[r];
    float* ob = out + (size_t)b * CDIM * NDIM + n0;
    #pragma unroll
    for (int kk = 0; kk < 4; kk++) {
        #pragma unroll
        for (int w = 0; w < 4; w++) {
            int c = 4 * (tj + 16 * kk) + w;
            float4* dst = (float4*)(ob + (size_t)c * NDIM + i0);
            float4 o4 = *dst;
            o4.x += acc[0][kk * 4 + w] * inv[0];
            o4.y += acc[1][kk * 4 + w] * inv[1];
            o4.z += acc[2][kk * 4 + w] * inv[2];
            o4.w += acc[3][kk * 4 + w] * inv[3];
            *dst = o4;
        }
    }
}

extern "C" void kernel_launch(void* const* d_in, const int* in_sizes, int n_in,
                              void* d_out, int out_size)
{
    const float* x  = (const float*)d_in[0];
    const float* Wq = (const float*)d_in[1];
    const float* bq = (const float*)d_in[2];
    const float* Wk = (const float*)d_in[3];
    const float* bk = (const float*)d_in[4];
    const float* Wv = (const float*)d_in[5];
    const float* bv = (const float*)d_in[6];
    const float* Wp = (const float*)d_in[7];
    const float* bp = (const float*)d_in[8];
    float* out = (float*)d_out;

    // 208KB dynamic smem for the attention kernel (idempotent, capture-safe)
    cudaFuncSetAttribute(attn_kernel,
                         cudaFuncAttributeMaxDynamicSharedMemorySize, 212992);

    // 1) q/k/v into scratch + proj into out (residual base)
    proj_kernel<<<dim3(32, 2, 32), 256>>>(x, Wq, bq, Wk, bk, Wv, bv, Wp, bp, out);
    // 2) flash attention, h accumulated into out
    attn_kernel<<<dim3(64, 8), 256, 212992>>>(out);
}